// round 16
// baseline (speedup 1.0000x reference)
#include <cuda_runtime.h>
#include <math.h>

#define DD 32
#define NMAX 100000
#define EMAX 800000
#define TBINS 2048
#define NB 6
#define NBLK 444       // prep grid (3 blocks/SM * 148, all resident)

__device__ float  g_hA[NMAX * DD];
__device__ float  g_hB[NMAX * DD];
__device__ float4 g_attr[EMAX];
__device__ float  g_len[EMAX];
__device__ float  g_tab[3 * (TBINS + 1)];
__device__ int    g_deg[NMAX];
__device__ int    g_off[NMAX + 1];
__device__ int    g_cursor[NMAX];
__device__ int    g_perm[EMAX];
__device__ int    g_srcp[EMAX];
__device__ float4 g_wpack[3 * EMAX];
__device__ int    g_ctr[4];
__device__ int    g_scanpart[512];
__device__ int          g_bar_count;
__device__ volatile int g_bar_gen;

#define SQRT3F 1.7320508075688772f
#define SMOOTH_CF 8.4335730691f
#define COMB_NORM 0.022821773229382f
#define TAB_SCALE 409.6f

typedef unsigned long long ull;

__device__ __forceinline__ ull ffma2(ull a, ull b, ull c)
{
    ull d;
    asm("fma.rn.f32x2 %0, %1, %2, %3;" : "=l"(d) : "l"(a), "l"(b), "l"(c));
    return d;
}
__device__ __forceinline__ ull pack2(float lo, float hi)
{
    ull d;
    asm("mov.b64 %0, {%1, %2};" : "=l"(d) : "f"(lo), "f"(hi));
    return d;
}
__device__ __forceinline__ float2 unpack2(ull v)
{
    float lo, hi;
    asm("mov.b64 {%0, %1}, %2;" : "=f"(lo), "=f"(hi) : "l"(v));
    return make_float2(lo, hi);
}

__device__ __forceinline__ void grid_barrier()
{
    __syncthreads();
    if (threadIdx.x == 0) {
        __threadfence();
        int gen = g_bar_gen;
        if (atomicAdd(&g_bar_count, 1) == NBLK - 1) {
            g_bar_count = 0;
            __threadfence();
            g_bar_gen = gen + 1;
        } else {
            while (g_bar_gen == gen) { __nanosleep(40); }
        }
        __threadfence();
    }
    __syncthreads();
}

// ---------------- persistent prep ------------------------------------------
__global__ __launch_bounds__(256) void prep_kernel(
    const float* __restrict__ pos,
    const int*   __restrict__ esrc,
    const int*   __restrict__ edst,
    const float* __restrict__ W1,
    const float* __restrict__ W2,
    const float* __restrict__ x,
    const float* __restrict__ We,
    int E, int N)
{
    __shared__ float Ws[16 * 32];
    __shared__ int   s_wsum[8];
    const int tid = threadIdx.x;
    const int bid = blockIdx.x;
    const int gthread = bid * 256 + tid;
    const int gstride = NBLK * 256;

    for (int e = gthread; e < E; e += gstride) {
        int s = esrc[e], d = edst[e];
        float vx = pos[s * 3 + 0] - pos[d * 3 + 0];
        float vy = pos[s * 3 + 1] - pos[d * 3 + 1];
        float vz = pos[s * 3 + 2] - pos[d * 3 + 2];
        float len = sqrtf(vx * vx + vy * vy + vz * vz);
        float inv = __fdividef(SQRT3F, len + 1e-9f);
        g_attr[e] = make_float4(vy * inv, vz * inv, vx * inv, len);
        g_len[e] = len;
        if (len > 0.0f && len < 5.0f)
            atomicAdd(&g_deg[d], 1);
    }
    for (int idx = gthread; idx < 3 * (TBINS + 1); idx += gstride) {
        int l = idx / (TBINS + 1);
        int b = idx % (TBINS + 1);
        float len = (float)b * (5.0f / TBINS);
        float t  = len * 2.2f;
        int   j1 = (int)t;
        float d0 = t - (float)j1;
        float d1 = d0 - 1.0f;
        float ej0 = SMOOTH_CF * __expf(-(__fdividef(1.f, 1.f + d0) + __fdividef(1.f, 1.f - d0)));
        float ej1 = SMOOTH_CF * __expf(-(__fdividef(1.f, 1.f + d1) + __fdividef(1.f, 1.f - d1)));
        int j0 = j1 - 1;
        if (j0 < 0) ej0 = 0.0f;
        if (j0 > 9) ej0 = 0.0f;
        if (j1 > 9) ej1 = 0.0f;
        j0 = min(max(j0, 0), 9);
        j1 = min(max(j1, 0), 9);
        const float* w1a = W1 + l * 640 + j0 * 64;
        const float* w1b = W1 + l * 640 + j1 * 64;
        const float* w2  = W2 + l * 64;
        float acc = 0.0f;
        #pragma unroll 8
        for (int h = 0; h < 64; h++) {
            float z  = fmaf(ej0, w1a[h], ej1 * w1b[h]);
            float sl = __fdividef(z, 1.0f + __expf(-z));
            acc = fmaf(sl, w2[h], acc);
        }
        g_tab[idx] = acc * 0.125f;
    }
    for (int i = tid; i < 512; i += 256) Ws[i] = We[i];
    __syncthreads();
    for (int gid = gthread; gid < N * 32; gid += gstride) {
        int n = gid >> 5, k = gid & 31;
        const float* xr = x + n * 16;
        float acc = 0.0f;
        #pragma unroll
        for (int i = 0; i < 16; i++) acc = fmaf(__ldg(&xr[i]), Ws[i * 32 + k], acc);
        g_hA[gid] = acc;
    }
    grid_barrier();

    int nsb = (N + 1023) / 1024;
    int4 v = make_int4(0, 0, 0, 0);
    int  my_excl = 0;
    int  nb0 = bid * 1024 + tid * 4;
    if (bid < nsb) {
        if (nb0 < N) v = *(const int4*)&g_deg[nb0];   // N % 4 == 0
        int s = v.x + v.y + v.z + v.w;
        int lane = tid & 31, wid = tid >> 5;
        int sc = s;
        #pragma unroll
        for (int o = 1; o < 32; o <<= 1) {
            int t = __shfl_up_sync(0xffffffffu, sc, o);
            if (lane >= o) sc += t;
        }
        if (lane == 31) s_wsum[wid] = sc;
        __syncthreads();
        if (wid == 0 && lane < 8) {
            int w = s_wsum[lane];
            int ws = w;
            #pragma unroll
            for (int o = 1; o < 8; o <<= 1) {
                int t = __shfl_up_sync(0xffu, ws, o);
                if (lane >= o) ws += t;
            }
            s_wsum[lane] = ws - w;
        }
        __syncthreads();
        my_excl = sc - s + s_wsum[wid];
        if (tid == 255) g_scanpart[bid] = sc + s_wsum[7];
        __syncthreads();
    }
    grid_barrier();

    if (bid == 0 && tid < 32) {
        int vals[4];
        int run_excl[4];
        int lsum = 0;
        #pragma unroll
        for (int j = 0; j < 4; j++) {
            int i = tid * 4 + j;
            vals[j] = (i < nsb) ? g_scanpart[i] : 0;
            run_excl[j] = lsum;
            lsum += vals[j];
        }
        int sc = lsum;
        #pragma unroll
        for (int o = 1; o < 32; o <<= 1) {
            int t = __shfl_up_sync(0xffffffffu, sc, o);
            if (tid >= o) sc += t;
        }
        int base = sc - lsum;
        #pragma unroll
        for (int j = 0; j < 4; j++) {
            int i = tid * 4 + j;
            if (i < nsb) g_scanpart[i] = base + run_excl[j];
        }
    }
    grid_barrier();

    if (bid < nsb && nb0 < N) {
        int run = g_scanpart[bid] + my_excl;
        g_cursor[nb0 + 0] = run; run += v.x; g_off[nb0 + 1] = run;
        g_cursor[nb0 + 1] = run; run += v.y; g_off[nb0 + 2] = run;
        g_cursor[nb0 + 2] = run; run += v.z; g_off[nb0 + 3] = run;
        g_cursor[nb0 + 3] = run; run += v.w; g_off[nb0 + 4] = run;
    }
    if (gthread == 0) g_off[0] = 0;
    grid_barrier();

    for (int e = gthread; e < E; e += gstride) {
        float len = g_len[e];
        if (len > 0.0f && len < 5.0f) {
            int p = atomicAdd(&g_cursor[edst[e]], 1);
            g_perm[p] = e;
        }
    }
    grid_barrier();

    for (int n = gthread; n < N; n += gstride) {
        int s = g_off[n], t = g_off[n + 1];
        for (int i = s + 1; i < t; i++) {
            int key = g_perm[i];
            int j = i - 1;
            while (j >= s && g_perm[j] > key) { g_perm[j + 1] = g_perm[j]; j--; }
            g_perm[j + 1] = key;
        }
        g_deg[n] = 0;
    }
    grid_barrier();

    int tot = g_off[N];
    for (int p = gthread; p < tot; p += gstride) {
        int eid = g_perm[p];
        g_srcp[p] = esrc[eid];
        float4 a = g_attr[eid];
        float u = a.w * TAB_SCALE;
        int b = (int)u;
        float f = u - (float)b;
        #pragma unroll
        for (int l = 0; l < 3; l++) {
            float t0 = g_tab[l * (TBINS + 1) + b];
            float t1 = g_tab[l * (TBINS + 1) + b + 1];
            float r = fmaf(f, t1 - t0, t0);
            g_wpack[l * EMAX + p] = make_float4(r, r * a.x, r * a.y, r * a.z);
        }
    }
    if (gthread == 0) { g_ctr[0] = 0; g_ctr[1] = 0; g_ctr[2] = 0; g_ctr[3] = 0; }
}

// -------- layer: cooperative record loads + SHFL broadcast edge loop --------
__global__ __launch_bounds__(256, 5) void layer_kernel(
    const float*  __restrict__ h_in, float* __restrict__ h_out,
    const float*  __restrict__ Wtp_l,
    const float4* __restrict__ wpack_l,
    int N, int cidx)
{
    __shared__ float4 Wsh4[1024];             // fp32 W[i,0..3,k] (16KB)
    __shared__ float4 s_sm[8 * NB * 32];      // staging (24KB)

    {
        float* stage = (float*)s_sm;          // coalesced linear stage (16KB)
        for (int t = threadIdx.x; t < 4096; t += blockDim.x) stage[t] = Wtp_l[t];
        __syncthreads();
        for (int t = threadIdx.x; t < 1024; t += blockDim.x) {
            int i = t >> 5, k = t & 31;
            const float* w = stage + i * 128;
            Wsh4[t] = make_float4(w[k], w[32 + k], w[64 + k], w[96 + k]);
        }
    }
    __syncthreads();

    int lane = threadIdx.x & 31;
    int wloc = threadIdx.x >> 5;
    float4* s_b = &s_sm[wloc * NB * 32];
    int nBatches = (N + NB - 1) / NB;

    for (;;) {
        int b;
        if (lane == 0) b = atomicAdd(&g_ctr[cidx], 1);
        b = __shfl_sync(0xffffffffu, b, 0);
        if (b >= nBatches) break;
        int n0 = b * NB;
        #pragma unroll 1
        for (int nd = 0; nd < NB; nd++) {
            int n = n0 + nd;
            ull c01 = 0, c23 = 0;
            if (n < N) {
                int e0 = g_off[n], e1 = g_off[n + 1];
                for (int base = e0; base < e1; base += 32) {
                    int cnt = min(32, e1 - base);
                    // cooperative coalesced record load (lanes 0..cnt-1)
                    int mysrc = 0;
                    ulonglong2 myw = make_ulonglong2(0, 0);
                    if (lane < cnt) {
                        mysrc = g_srcp[base + lane];
                        myw = *(const ulonglong2*)&wpack_l[base + lane];
                    }
                    int j = 0;
                    for (; j + 4 <= cnt; j += 4) {
                        int s0 = __shfl_sync(0xffffffffu, mysrc, j + 0);
                        int s1 = __shfl_sync(0xffffffffu, mysrc, j + 1);
                        int s2 = __shfl_sync(0xffffffffu, mysrc, j + 2);
                        int s3 = __shfl_sync(0xffffffffu, mysrc, j + 3);
                        float h0 = __ldg(&h_in[s0 * 32 + lane]);
                        float h1 = __ldg(&h_in[s1 * 32 + lane]);
                        float h2 = __ldg(&h_in[s2 * 32 + lane]);
                        float h3 = __ldg(&h_in[s3 * 32 + lane]);
                        ull wx0 = __shfl_sync(0xffffffffu, myw.x, j + 0);
                        ull wy0 = __shfl_sync(0xffffffffu, myw.y, j + 0);
                        ull wx1 = __shfl_sync(0xffffffffu, myw.x, j + 1);
                        ull wy1 = __shfl_sync(0xffffffffu, myw.y, j + 1);
                        ull wx2 = __shfl_sync(0xffffffffu, myw.x, j + 2);
                        ull wy2 = __shfl_sync(0xffffffffu, myw.y, j + 2);
                        ull wx3 = __shfl_sync(0xffffffffu, myw.x, j + 3);
                        ull wy3 = __shfl_sync(0xffffffffu, myw.y, j + 3);
                        ull h0p = pack2(h0, h0);
                        ull h1p = pack2(h1, h1);
                        ull h2p = pack2(h2, h2);
                        ull h3p = pack2(h3, h3);
                        c01 = ffma2(wx0, h0p, c01); c23 = ffma2(wy0, h0p, c23);
                        c01 = ffma2(wx1, h1p, c01); c23 = ffma2(wy1, h1p, c23);
                        c01 = ffma2(wx2, h2p, c01); c23 = ffma2(wy2, h2p, c23);
                        c01 = ffma2(wx3, h3p, c01); c23 = ffma2(wy3, h3p, c23);
                    }
                    for (; j < cnt; j++) {
                        int s = __shfl_sync(0xffffffffu, mysrc, j);
                        ull wx = __shfl_sync(0xffffffffu, myw.x, j);
                        ull wy = __shfl_sync(0xffffffffu, myw.y, j);
                        float h = __ldg(&h_in[s * 32 + lane]);
                        ull hp = pack2(h, h);
                        c01 = ffma2(wx, hp, c01);
                        c23 = ffma2(wy, hp, c23);
                    }
                }
            }
            ulonglong2 cc; cc.x = c01; cc.y = c23;
            *(ulonglong2*)&s_b[nd * 32 + lane] = cc;
        }
        __syncwarp();
        ull ang2[NB];
        #pragma unroll
        for (int nd = 0; nd < NB; nd++) ang2[nd] = 0;
        #pragma unroll 8
        for (int i = 0; i < 32; i++) {
            ulonglong2 wv = *(const ulonglong2*)&Wsh4[i * 32 + lane];
            #pragma unroll
            for (int nd = 0; nd < NB; nd++) {
                ulonglong2 sv = *(const ulonglong2*)&s_b[nd * 32 + i];
                ang2[nd] = ffma2(sv.x, wv.x, ang2[nd]);
                ang2[nd] = ffma2(sv.y, wv.y, ang2[nd]);
            }
        }
        __syncwarp();
        #pragma unroll
        for (int nd = 0; nd < NB; nd++) {
            int n = n0 + nd;
            if (n < N) {
                float2 a = unpack2(ang2[nd]);
                h_out[n * 32 + lane] = h_in[n * 32 + lane] + COMB_NORM * (a.x + a.y);
            }
        }
    }
}

__global__ void pool_kernel(const float* __restrict__ h,
                            const float* __restrict__ ori,
                            const float* __restrict__ Wdec,
                            const int*   __restrict__ batch,
                            float* __restrict__ out, int N)
{
    int g = blockIdx.x;
    __shared__ int s_range[2];
    __shared__ float s_part[8][32];
    int tid = threadIdx.x, lane = tid & 31, wid = tid >> 5;
    if (tid < 2) {
        int key = g + tid;
        int lo = 0, hi = N;
        while (lo < hi) { int m = (lo + hi) >> 1; if (batch[m] < key) lo = m + 1; else hi = m; }
        s_range[tid] = lo;
    }
    __syncthreads();
    int st = s_range[0], en = s_range[1];
    float sum = 0.0f;
    for (int n = st + wid; n < en; n += 8) sum += __ldg(&h[n * 32 + lane]);
    s_part[wid][lane] = sum;
    __syncthreads();
    if (wid == 0) {
        float tot = 0.0f;
        #pragma unroll
        for (int w = 0; w < 8; w++) tot += s_part[w][lane];
        int cnt = en - st;
        float gk = tot / fmaxf((float)cnt, 1.0f);
        float c0 = gk * Wdec[lane * 4 + 0];
        float c1 = gk * Wdec[lane * 4 + 1];
        float c2 = gk * Wdec[lane * 4 + 2];
        float c3 = gk * Wdec[lane * 4 + 3];
        #pragma unroll
        for (int o = 16; o > 0; o >>= 1) {
            c0 += __shfl_xor_sync(0xffffffffu, c0, o);
            c1 += __shfl_xor_sync(0xffffffffu, c1, o);
            c2 += __shfl_xor_sync(0xffffffffu, c2, o);
            c3 += __shfl_xor_sync(0xffffffffu, c3, o);
        }
        if (lane == 0) {
            float th = ori[g * 2], ph = ori[g * 2 + 1];
            float sth = sinf(th), cth = cosf(th), sph = sinf(ph), cph = cosf(ph);
            float qx = sth * cph, qy = sth * sph, qz = cth;
            out[g] = c0 + SQRT3F * (c1 * qy + c2 * qz + c3 * qx);
        }
    }
}

extern "C" void kernel_launch(void* const* d_in, const int* in_sizes, int n_in,
                              void* d_out, int out_size)
{
    const float* pos     = (const float*)d_in[0];
    const float* x       = (const float*)d_in[1];
    const float* ori     = (const float*)d_in[2];
    const float* W_embed = (const float*)d_in[3];
    const float* W_tp    = (const float*)d_in[4];
    const float* W_fc1   = (const float*)d_in[5];
    const float* W_fc2   = (const float*)d_in[6];
    const float* W_dec   = (const float*)d_in[7];
    const int*   esrc    = (const int*)d_in[8];
    const int*   edst    = (const int*)d_in[9];
    const int*   batch   = (const int*)d_in[10];
    int N = in_sizes[10];
    int E = in_sizes[8];
    int G = in_sizes[2] / 2;
    float* out = (float*)d_out;

    void *hA, *hB, *wpk;
    cudaGetSymbolAddress(&hA, g_hA);
    cudaGetSymbolAddress(&hB, g_hB);
    cudaGetSymbolAddress(&wpk, g_wpack);
    const float4* wpack = (const float4*)wpk;

    prep_kernel<<<NBLK, 256>>>(pos, esrc, edst, W_fc1, W_fc2, x, W_embed, E, N);
    layer_kernel<<<740, 256>>>((const float*)hA, (float*)hB, W_tp + 0 * 4096, wpack + 0 * EMAX, N, 0);
    layer_kernel<<<740, 256>>>((const float*)hB, (float*)hA, W_tp + 1 * 4096, wpack + 1 * EMAX, N, 1);
    layer_kernel<<<740, 256>>>((const float*)hA, (float*)hB, W_tp + 2 * 4096, wpack + 2 * EMAX, N, 2);
    pool_kernel<<<G, 256>>>((const float*)hB, ori, W_dec, batch, out, N);
}

// round 17
// speedup vs baseline: 1.0564x; 1.0564x over previous
#include <cuda_runtime.h>
#include <cuda_fp16.h>
#include <math.h>

#define DD 32
#define NMAX 100000
#define EMAX 800000
#define TBINS 2048
#define NB 6
#define NBLK 444

__device__ float  g_hA[NMAX * DD];
__device__ float  g_hB[NMAX * DD];
__device__ float4 g_attr[EMAX];
__device__ float  g_len[EMAX];
__device__ float  g_tab[3 * (TBINS + 1)];
__device__ int    g_deg[NMAX];
__device__ int    g_off[NMAX + 1];
__device__ int    g_cursor[NMAX];
__device__ int    g_perm[EMAX];
__device__ int    g_srcp[EMAX];
__device__ float4 g_wpack[3 * EMAX];
__device__ int    g_ctr[4];
__device__ int    g_scanpart[512];
__device__ int          g_bar_count;
__device__ volatile int g_bar_gen;

#define SQRT3F 1.7320508075688772f
#define SMOOTH_CF 8.4335730691f
#define COMB_NORM 0.022821773229382f
#define TAB_SCALE 409.6f

typedef unsigned long long ull;

__device__ __forceinline__ ull ffma2(ull a, ull b, ull c)
{
    ull d;
    asm("fma.rn.f32x2 %0, %1, %2, %3;" : "=l"(d) : "l"(a), "l"(b), "l"(c));
    return d;
}
__device__ __forceinline__ ull pack2(float lo, float hi)
{
    ull d;
    asm("mov.b64 %0, {%1, %2};" : "=l"(d) : "f"(lo), "f"(hi));
    return d;
}
__device__ __forceinline__ float2 unpack2(ull v)
{
    float lo, hi;
    asm("mov.b64 {%0, %1}, %2;" : "=f"(lo), "=f"(hi) : "l"(v));
    return make_float2(lo, hi);
}

__device__ __forceinline__ void grid_barrier()
{
    __syncthreads();
    if (threadIdx.x == 0) {
        __threadfence();
        int gen = g_bar_gen;
        if (atomicAdd(&g_bar_count, 1) == NBLK - 1) {
            g_bar_count = 0;
            __threadfence();
            g_bar_gen = gen + 1;
        } else {
            while (g_bar_gen == gen) { __nanosleep(40); }
        }
        __threadfence();
    }
    __syncthreads();
}

__global__ __launch_bounds__(256) void prep_kernel(
    const float* __restrict__ pos,
    const int*   __restrict__ esrc,
    const int*   __restrict__ edst,
    const float* __restrict__ W1,
    const float* __restrict__ W2,
    const float* __restrict__ x,
    const float* __restrict__ We,
    int E, int N)
{
    __shared__ float Ws[16 * 32];
    __shared__ int   s_wsum[8];
    const int tid = threadIdx.x;
    const int bid = blockIdx.x;
    const int gthread = bid * 256 + tid;
    const int gstride = NBLK * 256;

    for (int e = gthread; e < E; e += gstride) {
        int s = esrc[e], d = edst[e];
        float vx = pos[s * 3 + 0] - pos[d * 3 + 0];
        float vy = pos[s * 3 + 1] - pos[d * 3 + 1];
        float vz = pos[s * 3 + 2] - pos[d * 3 + 2];
        float len = sqrtf(vx * vx + vy * vy + vz * vz);
        float inv = __fdividef(SQRT3F, len + 1e-9f);
        g_attr[e] = make_float4(vy * inv, vz * inv, vx * inv, len);
        g_len[e] = len;
        if (len > 0.0f && len < 5.0f)
            atomicAdd(&g_deg[d], 1);
    }
    for (int idx = gthread; idx < 3 * (TBINS + 1); idx += gstride) {
        int l = idx / (TBINS + 1);
        int b = idx % (TBINS + 1);
        float len = (float)b * (5.0f / TBINS);
        float t  = len * 2.2f;
        int   j1 = (int)t;
        float d0 = t - (float)j1;
        float d1 = d0 - 1.0f;
        float ej0 = SMOOTH_CF * __expf(-(__fdividef(1.f, 1.f + d0) + __fdividef(1.f, 1.f - d0)));
        float ej1 = SMOOTH_CF * __expf(-(__fdividef(1.f, 1.f + d1) + __fdividef(1.f, 1.f - d1)));
        int j0 = j1 - 1;
        if (j0 < 0) ej0 = 0.0f;
        if (j0 > 9) ej0 = 0.0f;
        if (j1 > 9) ej1 = 0.0f;
        j0 = min(max(j0, 0), 9);
        j1 = min(max(j1, 0), 9);
        const float* w1a = W1 + l * 640 + j0 * 64;
        const float* w1b = W1 + l * 640 + j1 * 64;
        const float* w2  = W2 + l * 64;
        float acc = 0.0f;
        #pragma unroll 8
        for (int h = 0; h < 64; h++) {
            float z  = fmaf(ej0, w1a[h], ej1 * w1b[h]);
            float sl = __fdividef(z, 1.0f + __expf(-z));
            acc = fmaf(sl, w2[h], acc);
        }
        g_tab[idx] = acc * 0.125f;
    }
    for (int i = tid; i < 512; i += 256) Ws[i] = We[i];
    __syncthreads();
    for (int gid = gthread; gid < N * 32; gid += gstride) {
        int n = gid >> 5, k = gid & 31;
        const float* xr = x + n * 16;
        float acc = 0.0f;
        #pragma unroll
        for (int i = 0; i < 16; i++) acc = fmaf(__ldg(&xr[i]), Ws[i * 32 + k], acc);
        g_hA[gid] = acc;
    }
    grid_barrier();

    int nsb = (N + 1023) / 1024;
    int4 v = make_int4(0, 0, 0, 0);
    int  my_excl = 0;
    int  nb0 = bid * 1024 + tid * 4;
    if (bid < nsb) {
        if (nb0 < N) v = *(const int4*)&g_deg[nb0];
        int s = v.x + v.y + v.z + v.w;
        int lane = tid & 31, wid = tid >> 5;
        int sc = s;
        #pragma unroll
        for (int o = 1; o < 32; o <<= 1) {
            int t = __shfl_up_sync(0xffffffffu, sc, o);
            if (lane >= o) sc += t;
        }
        if (lane == 31) s_wsum[wid] = sc;
        __syncthreads();
        if (wid == 0 && lane < 8) {
            int w = s_wsum[lane];
            int ws = w;
            #pragma unroll
            for (int o = 1; o < 8; o <<= 1) {
                int t = __shfl_up_sync(0xffu, ws, o);
                if (lane >= o) ws += t;
            }
            s_wsum[lane] = ws - w;
        }
        __syncthreads();
        my_excl = sc - s + s_wsum[wid];
        if (tid == 255) g_scanpart[bid] = sc + s_wsum[7];
        __syncthreads();
    }
    grid_barrier();

    if (bid == 0 && tid < 32) {
        int vals[4];
        int run_excl[4];
        int lsum = 0;
        #pragma unroll
        for (int j = 0; j < 4; j++) {
            int i = tid * 4 + j;
            vals[j] = (i < nsb) ? g_scanpart[i] : 0;
            run_excl[j] = lsum;
            lsum += vals[j];
        }
        int sc = lsum;
        #pragma unroll
        for (int o = 1; o < 32; o <<= 1) {
            int t = __shfl_up_sync(0xffffffffu, sc, o);
            if (tid >= o) sc += t;
        }
        int base = sc - lsum;
        #pragma unroll
        for (int j = 0; j < 4; j++) {
            int i = tid * 4 + j;
            if (i < nsb) g_scanpart[i] = base + run_excl[j];
        }
    }
    grid_barrier();

    if (bid < nsb && nb0 < N) {
        int run = g_scanpart[bid] + my_excl;
        g_cursor[nb0 + 0] = run; run += v.x; g_off[nb0 + 1] = run;
        g_cursor[nb0 + 1] = run; run += v.y; g_off[nb0 + 2] = run;
        g_cursor[nb0 + 2] = run; run += v.z; g_off[nb0 + 3] = run;
        g_cursor[nb0 + 3] = run; run += v.w; g_off[nb0 + 4] = run;
    }
    if (gthread == 0) g_off[0] = 0;
    grid_barrier();

    for (int e = gthread; e < E; e += gstride) {
        float len = g_len[e];
        if (len > 0.0f && len < 5.0f) {
            int p = atomicAdd(&g_cursor[edst[e]], 1);
            g_perm[p] = e;
        }
    }
    grid_barrier();

    for (int n = gthread; n < N; n += gstride) {
        int s = g_off[n], t = g_off[n + 1];
        for (int i = s + 1; i < t; i++) {
            int key = g_perm[i];
            int j = i - 1;
            while (j >= s && g_perm[j] > key) { g_perm[j + 1] = g_perm[j]; j--; }
            g_perm[j + 1] = key;
        }
        g_deg[n] = 0;
    }
    grid_barrier();

    int tot = g_off[N];
    for (int p = gthread; p < tot; p += gstride) {
        int eid = g_perm[p];
        g_srcp[p] = esrc[eid];
        float4 a = g_attr[eid];
        float u = a.w * TAB_SCALE;
        int b = (int)u;
        float f = u - (float)b;
        #pragma unroll
        for (int l = 0; l < 3; l++) {
            float t0 = g_tab[l * (TBINS + 1) + b];
            float t1 = g_tab[l * (TBINS + 1) + b + 1];
            float r = fmaf(f, t1 - t0, t0);
            g_wpack[l * EMAX + p] = make_float4(r, r * a.x, r * a.y, r * a.z);
        }
    }
    if (gthread == 0) { g_ctr[0] = 0; g_ctr[1] = 0; g_ctr[2] = 0; g_ctr[3] = 0; }
}

__global__ __launch_bounds__(256, 5) void layer_kernel(
    const float*  __restrict__ h_in, float* __restrict__ h_out,
    const float*  __restrict__ Wtp_l,
    const float4* __restrict__ wpack_l,
    int N, int cidx)
{
    __shared__ uint2  Wsh2[1024];             // half4 W[i,0..3,k] (8KB)
    __shared__ float4 s_sm[8 * NB * 32];      // staging (24KB)

    {
        float* stage = (float*)s_sm;          // coalesced linear stage (16KB)
        for (int t = threadIdx.x; t < 4096; t += blockDim.x) stage[t] = Wtp_l[t];
        __syncthreads();
        for (int t = threadIdx.x; t < 1024; t += blockDim.x) {
            int i = t >> 5, k = t & 31;
            const float* w = stage + i * 128;
            __half2 lo = __floats2half2_rn(w[k],      w[32 + k]);
            __half2 hi = __floats2half2_rn(w[64 + k], w[96 + k]);
            Wsh2[t] = make_uint2(*(const unsigned*)&lo, *(const unsigned*)&hi);
        }
    }
    __syncthreads();

    int lane = threadIdx.x & 31;
    int wloc = threadIdx.x >> 5;
    float4* s_b = &s_sm[wloc * NB * 32];
    int nBatches = (N + NB - 1) / NB;

    for (;;) {
        int b;
        if (lane == 0) b = atomicAdd(&g_ctr[cidx], 1);
        b = __shfl_sync(0xffffffffu, b, 0);
        if (b >= nBatches) break;
        int n0 = b * NB;
        #pragma unroll 1
        for (int nd = 0; nd < NB; nd++) {
            int n = n0 + nd;
            ull c01 = 0, c23 = 0;
            if (n < N) {
                int e0 = g_off[n], e1 = g_off[n + 1];
                int p = e0;
                for (; p + 4 <= e1; p += 4) {
                    int  sA = __ldg(&g_srcp[p]);
                    int  sB = __ldg(&g_srcp[p + 1]);
                    int  sC = __ldg(&g_srcp[p + 2]);
                    int  sD = __ldg(&g_srcp[p + 3]);
                    ulonglong2 wA = __ldg((const ulonglong2*)&wpack_l[p]);
                    ulonglong2 wB = __ldg((const ulonglong2*)&wpack_l[p + 1]);
                    ulonglong2 wC = __ldg((const ulonglong2*)&wpack_l[p + 2]);
                    ulonglong2 wD = __ldg((const ulonglong2*)&wpack_l[p + 3]);
                    float hA = __ldg(&h_in[sA * 32 + lane]);
                    float hB = __ldg(&h_in[sB * 32 + lane]);
                    float hC = __ldg(&h_in[sC * 32 + lane]);
                    float hD = __ldg(&h_in[sD * 32 + lane]);
                    ull hA2 = pack2(hA, hA);
                    ull hB2 = pack2(hB, hB);
                    ull hC2 = pack2(hC, hC);
                    ull hD2 = pack2(hD, hD);
                    c01 = ffma2(wA.x, hA2, c01); c23 = ffma2(wA.y, hA2, c23);
                    c01 = ffma2(wB.x, hB2, c01); c23 = ffma2(wB.y, hB2, c23);
                    c01 = ffma2(wC.x, hC2, c01); c23 = ffma2(wC.y, hC2, c23);
                    c01 = ffma2(wD.x, hD2, c01); c23 = ffma2(wD.y, hD2, c23);
                }
                for (; p < e1; p++) {
                    int s = __ldg(&g_srcp[p]);
                    ulonglong2 w = __ldg((const ulonglong2*)&wpack_l[p]);
                    float h = __ldg(&h_in[s * 32 + lane]);
                    ull h2 = pack2(h, h);
                    c01 = ffma2(w.x, h2, c01);
                    c23 = ffma2(w.y, h2, c23);
                }
            }
            ulonglong2 cc; cc.x = c01; cc.y = c23;
            *(ulonglong2*)&s_b[nd * 32 + lane] = cc;
        }
        __syncwarp();
        ull ang2[NB];
        #pragma unroll
        for (int nd = 0; nd < NB; nd++) ang2[nd] = 0;
        #pragma unroll 8
        for (int i = 0; i < 32; i++) {
            uint2 wp = Wsh2[i * 32 + lane];
            float2 w01 = __half22float2(*(const __half2*)&wp.x);
            float2 w23 = __half22float2(*(const __half2*)&wp.y);
            ull w01p = pack2(w01.x, w01.y);
            ull w23p = pack2(w23.x, w23.y);
            #pragma unroll
            for (int nd = 0; nd < NB; nd++) {
                ulonglong2 sv = *(const ulonglong2*)&s_b[nd * 32 + i];
                ang2[nd] = ffma2(sv.x, w01p, ang2[nd]);
                ang2[nd] = ffma2(sv.y, w23p, ang2[nd]);
            }
        }
        __syncwarp();
        #pragma unroll
        for (int nd = 0; nd < NB; nd++) {
            int n = n0 + nd;
            if (n < N) {
                float2 a = unpack2(ang2[nd]);
                h_out[n * 32 + lane] = h_in[n * 32 + lane] + COMB_NORM * (a.x + a.y);
            }
        }
    }
}

__global__ void pool_kernel(const float* __restrict__ h,
                            const float* __restrict__ ori,
                            const float* __restrict__ Wdec,
                            const int*   __restrict__ batch,
                            float* __restrict__ out, int N)
{
    int g = blockIdx.x;
    __shared__ int s_range[2];
    __shared__ float s_part[8][32];
    int tid = threadIdx.x, lane = tid & 31, wid = tid >> 5;
    if (tid < 2) {
        int key = g + tid;
        int lo = 0, hi = N;
        while (lo < hi) { int m = (lo + hi) >> 1; if (batch[m] < key) lo = m + 1; else hi = m; }
        s_range[tid] = lo;
    }
    __syncthreads();
    int st = s_range[0], en = s_range[1];
    float sum = 0.0f;
    for (int n = st + wid; n < en; n += 8) sum += __ldg(&h[n * 32 + lane]);
    s_part[wid][lane] = sum;
    __syncthreads();
    if (wid == 0) {
        float tot = 0.0f;
        #pragma unroll
        for (int w = 0; w < 8; w++) tot += s_part[w][lane];
        int cnt = en - st;
        float gk = tot / fmaxf((float)cnt, 1.0f);
        float c0 = gk * Wdec[lane * 4 + 0];
        float c1 = gk * Wdec[lane * 4 + 1];
        float c2 = gk * Wdec[lane * 4 + 2];
        float c3 = gk * Wdec[lane * 4 + 3];
        #pragma unroll
        for (int o = 16; o > 0; o >>= 1) {
            c0 += __shfl_xor_sync(0xffffffffu, c0, o);
            c1 += __shfl_xor_sync(0xffffffffu, c1, o);
            c2 += __shfl_xor_sync(0xffffffffu, c2, o);
            c3 += __shfl_xor_sync(0xffffffffu, c3, o);
        }
        if (lane == 0) {
            float th = ori[g * 2], ph = ori[g * 2 + 1];
            float sth = sinf(th), cth = cosf(th), sph = sinf(ph), cph = cosf(ph);
            float qx = sth * cph, qy = sth * sph, qz = cth;
            out[g] = c0 + SQRT3F * (c1 * qy + c2 * qz + c3 * qx);
        }
    }
}

extern "C" void kernel_launch(void* const* d_in, const int* in_sizes, int n_in,
                              void* d_out, int out_size)
{
    const float* pos     = (const float*)d_in[0];
    const float* x       = (const float*)d_in[1];
    const float* ori     = (const float*)d_in[2];
    const float* W_embed = (const float*)d_in[3];
    const float* W_tp    = (const float*)d_in[4];
    const float* W_fc1   = (const float*)d_in[5];
    const float* W_fc2   = (const float*)d_in[6];
    const float* W_dec   = (const float*)d_in[7];
    const int*   esrc    = (const int*)d_in[8];
    const int*   edst    = (const int*)d_in[9];
    const int*   batch   = (const int*)d_in[10];
    int N = in_sizes[10];
    int E = in_sizes[8];
    int G = in_sizes[2] / 2;
    float* out = (float*)d_out;

    void *hA, *hB, *wpk;
    cudaGetSymbolAddress(&hA, g_hA);
    cudaGetSymbolAddress(&hB, g_hB);
    cudaGetSymbolAddress(&wpk, g_wpack);
    const float4* wpack = (const float4*)wpk;

    prep_kernel<<<NBLK, 256>>>(pos, esrc, edst, W_fc1, W_fc2, x, W_embed, E, N);
    layer_kernel<<<740, 256>>>((const float*)hA, (float*)hB, W_tp + 0 * 4096, wpack + 0 * EMAX, N, 0);
    layer_kernel<<<740, 256>>>((const float*)hB, (float*)hA, W_tp + 1 * 4096, wpack + 1 * EMAX, N, 1);
    layer_kernel<<<740, 256>>>((const float*)hA, (float*)hB, W_tp + 2 * 4096, wpack + 2 * EMAX, N, 2);
    pool_kernel<<<G, 256>>>((const float*)hB, ori, W_dec, batch, out, N);
}